// round 9
// baseline (speedup 1.0000x reference)
#include <cuda_runtime.h>
#include <math.h>

// ---------------------------------------------------------------------------
// CombinedLoss: 0.5*mean|o-t| + 0.5*mean|CWT(o)-CWT(t)| (real morlet, 36 widths)
// CWT(o)-CWT(t) = CWT(d), d=o-t.  'same' conv with reversed kernel ==
// correlation with un-reversed morlet:
//   conv_w[i] = sum_{p=0}^{10w-1} mor_w[p] * d[i + p - 5w]   (zero padded)
// Round 9: packed fma.rn.f32x2 engine; 8 balanced width-groups (1640 blocks
// -> fills the 7-CTA/SM register-limited residency); K prefetch distance 2.
// ---------------------------------------------------------------------------

#define L_TOTAL   262144
#define THREADS   128
#define RBLK      10
#define TILE      (THREADS * RBLK)                // 1280
#define NBX       ((L_TOTAL + TILE - 1) / TILE)   // 205
#define NGRP      8
#define TOTALB    (NGRP * NBX)                    // 1640
#define SD_DECL   (TILE + 2 * 180 + 24)           // 1664
#define SK_DECL   1000                            // max group tap count 990

typedef unsigned long long ull;

__device__ float g_cwt_part[NGRP * NBX];
__device__ float g_wave_part[NBX];
__device__ unsigned int g_done;                   // zero-init; reset each run

// 8 groups, balanced taps: 910,800,820,720,810,900,990,710. All H even.
__constant__ int c_w0[NGRP] = {1, 14, 19, 23, 26, 29, 32, 35};
__constant__ int c_w1[NGRP] = {14, 19, 23, 26, 29, 32, 35, 37};
__constant__ int c_H [NGRP] = {66, 90, 110, 126, 140, 156, 170, 180};

// ======================= constexpr morlet coefficients ======================
__host__ __device__ constexpr double cabs_(double v) { return v < 0.0 ? -v : v; }

__host__ __device__ constexpr double cexp_(double xx) {
    if (xx < -120.0) return 0.0;
    const double LN2_HI = 6.93147180369123816490e-01;
    const double LN2_LO = 1.90821492927058770002e-10;
    const double INV_LN2 = 1.44269504088896338700e+00;
    double nd = xx * INV_LN2;
    int n = (int)(nd >= 0.0 ? nd + 0.5 : nd - 0.5);
    double r = (xx - (double)n * LN2_HI) - (double)n * LN2_LO;
    double term = 1.0, sum = 1.0;
    for (int i = 1; i <= 18; ++i) {
        term *= r / (double)i;
        sum += term;
        if (cabs_(term) < 1e-60) break;
    }
    double p = 1.0, b = (n < 0) ? 0.5 : 2.0;
    int m = (n < 0) ? -n : n;
    while (m) { if (m & 1) p *= b; m >>= 1; if (m) b *= b; }
    return sum * p;
}
__host__ __device__ constexpr double ccos_(double xx) {
    const double PIO2_1  = 1.57079632673412561417e+00;
    const double PIO2_1t = 6.07710050650619224932e-11;
    double ax = xx < 0.0 ? -xx : xx;
    int q = (int)(ax * 0.63661977236758134308 + 0.5);
    double r = (ax - (double)q * PIO2_1) - (double)q * PIO2_1t;
    double r2 = r * r;
    double cs = 1.0, tc = 1.0;
    for (int i = 1; i <= 10; ++i) {
        tc *= -r2 / (double)((2 * i - 1) * (2 * i));
        cs += tc;
        if (cabs_(tc) < 1e-60) break;
    }
    double sn = r, ts = r;
    for (int i = 1; i <= 10; ++i) {
        ts *= -r2 / (double)((2 * i) * (2 * i + 1));
        sn += ts;
        if (cabs_(ts) < 1e-60) break;
    }
    int quad = q & 3;
    return quad == 0 ? cs : quad == 1 ? -sn : quad == 2 ? -cs : sn;
}
__host__ __device__ constexpr double morlet_tap(int w, int p) {
    const double TWO_PI = 6.28318530717958647692;
    const double PI_M025 = 0.75112554446494248286;
    int N = 10 * w;
    double step = (2.0 * TWO_PI) / (double)(N - 1);
    double x = -TWO_PI + (double)p * step;
    double ew = cexp_(-0.5 * (double)(w * w));
    return (ccos_((double)w * x) - ew) * cexp_(-0.5 * x * x) * PI_M025;
}

template<int W> struct Ker { float k[10 * W]; };
template<int W>
__host__ __device__ constexpr Ker<W> make_ker() {
    Ker<W> t{};
    for (int p = 0; p < 10 * W; ++p) t.k[p] = (float)morlet_tap(W, p);
    return t;
}

#define DEFK(W) __device__ const Ker<W> g_k##W = make_ker<W>();
DEFK(1)  DEFK(2)  DEFK(3)  DEFK(4)  DEFK(5)  DEFK(6)  DEFK(7)  DEFK(8)
DEFK(9)  DEFK(10) DEFK(11) DEFK(12) DEFK(13) DEFK(14) DEFK(15) DEFK(16)
DEFK(17) DEFK(18) DEFK(19) DEFK(20) DEFK(21) DEFK(22) DEFK(23) DEFK(24)
DEFK(25) DEFK(26) DEFK(27) DEFK(28) DEFK(29) DEFK(30) DEFK(31) DEFK(32)
DEFK(33) DEFK(34) DEFK(35) DEFK(36)
#undef DEFK

__device__ const float* const g_kptr[37] = {
    nullptr,
    g_k1.k,  g_k2.k,  g_k3.k,  g_k4.k,  g_k5.k,  g_k6.k,  g_k7.k,  g_k8.k,
    g_k9.k,  g_k10.k, g_k11.k, g_k12.k, g_k13.k, g_k14.k, g_k15.k, g_k16.k,
    g_k17.k, g_k18.k, g_k19.k, g_k20.k, g_k21.k, g_k22.k, g_k23.k, g_k24.k,
    g_k25.k, g_k26.k, g_k27.k, g_k28.k, g_k29.k, g_k30.k, g_k31.k, g_k32.k,
    g_k33.k, g_k34.k, g_k35.k, g_k36.k
};

// ---------- packed f32x2 helpers ----------
__device__ __forceinline__ void ffma2(ull& d, ull a, ull b) {
    asm("fma.rn.f32x2 %0, %1, %2, %0;" : "+l"(d) : "l"(a), "l"(b));
}
__device__ __forceinline__ float lo_f(ull v) {
    float a, b; asm("mov.b64 {%0, %1}, %2;" : "=f"(a), "=f"(b) : "l"(v)); return a;
}
__device__ __forceinline__ float hi_f(ull v) {
    float a, b; asm("mov.b64 {%0, %1}, %2;" : "=f"(a), "=f"(b) : "l"(v)); return b;
}
__device__ __forceinline__ ull ld64s(const float* p) {
    return *reinterpret_cast<const ull*>(p);
}

// ============================ packed tap engine =============================
// A[r].lo even taps, A[r].hi odd taps for output r. E pairs from sd, F pairs
// from sd2 (shifted copy): every access is an aligned LDS.64, zero repacking.
// K prefetched TWO pairs ahead (~25 instr > 29-cyc LDS latency).
__device__ float do_width_rt(const float* __restrict__ bE,
                             const float* __restrict__ bF,
                             const float* __restrict__ bK,
                             int W, int gi0) {
    ull E[5], F[5], A[10];
    #pragma unroll
    for (int j = 0; j < 5; ++j) { E[j] = ld64s(bE + 2 * j); F[j] = ld64s(bF + 2 * j); }
    #pragma unroll
    for (int r = 0; r < 10; ++r) A[r] = 0ULL;

    ull Ka = ld64s(bK);
    ull Kb = ld64s(bK + 2);
    #pragma unroll 1
    for (int i = 0; i < W; ++i) {                  // 5 tap-pairs / iteration
        #pragma unroll
        for (int j = 0; j < 5; ++j) {
            ull Kc = ld64s(bK + 2 * (j + 2));      // prefetch distance 2
            #pragma unroll
            for (int h = 0; h < 5; ++h) {
                ffma2(A[2 * h],     Ka, E[(j + h) % 5]);
                ffma2(A[2 * h + 1], Ka, F[(j + h) % 5]);
            }
            E[j] = ld64s(bE + 2 * j + 10);         // pair m+5 refill
            F[j] = ld64s(bF + 2 * j + 10);
            Ka = Kb; Kb = Kc;                      // renamed by unroll
        }
        bE += 10; bF += 10; bK += 10;
    }

    float s = 0.f;
    #pragma unroll
    for (int r = 0; r < 10; ++r)
        if (gi0 + r < L_TOTAL) s += fabsf(lo_f(A[r]) + hi_f(A[r]));
    return s;
}

__device__ __forceinline__ float warp_sum(float v) {
    #pragma unroll
    for (int o = 16; o > 0; o >>= 1) v += __shfl_xor_sync(0xFFFFFFFFu, v, o);
    return v;
}

// ---------------------------------------------------------------------------
__global__ void __launch_bounds__(THREADS, 6)
cwt_kernel(const float* __restrict__ o, const float* __restrict__ t,
           float* __restrict__ out) {
    __shared__ __align__(8) float sd [SD_DECL];
    __shared__ __align__(8) float sd2[SD_DECL];
    __shared__ __align__(8) float sk [SK_DECL];
    __shared__ float s_red[8];
    __shared__ unsigned s_last;

    const int gy = blockIdx.y;
    const int H  = c_H[gy];
    const int w0 = c_w0[gy];
    const int w1 = c_w1[gy];
    const int tile0 = blockIdx.x * TILE;
    const int tid = threadIdx.x;

    // Diff with halo, zero-padded to SD_DECL; shifted copy; fused |d| (gy 0)
    const int span = TILE + 2 * H;
    float wsum = 0.f;
    for (int j = tid; j < SD_DECL; j += THREADS) {
        int g = tile0 - H + j;
        float v = 0.f;
        if (j < span && g >= 0 && g < L_TOTAL) v = o[g] - t[g];
        sd[j] = v;
        if (j > 0) sd2[j - 1] = v;
        if (j == SD_DECL - 1) sd2[SD_DECL - 1] = 0.f;
        if (gy == 0 && j >= H && j < H + TILE && g < L_TOTAL) wsum += fabsf(v);
    }

    // This group's coefficient tables -> shared (flat, coalesced)
    const int koff0 = 5 * w0 * (w0 - 1);
    {
        int off = 0;
        for (int w = w0; w < w1; ++w) {
            const float* src = g_kptr[w];
            for (int p = tid; p < 10 * w; p += THREADS) sk[off + p] = src[p];
            off += 10 * w;
        }
    }
    __syncthreads();

    const int base = H + tid * RBLK;
    const int gi0  = tile0 + tid * RBLK;

    float csum = 0.f;
    #pragma unroll 1
    for (int w = w0; w < w1; ++w) {
        const int s0 = base - 5 * w;
        const int odd = w & 1;                     // H even: parity(s0)=parity(w)
        const float* bE = odd ? (sd2 + (s0 - 1)) : (sd + s0);
        const float* bF = odd ? (sd + (s0 + 1)) : (sd2 + s0);
        const float* bK = sk + (5 * w * (w - 1) - koff0);
        csum += do_width_rt(bE, bF, bK, w, gi0);
    }

    // Block reduction -> per-block partial slots
    csum = warp_sum(csum);
    wsum = warp_sum(wsum);
    const int lane = tid & 31, wrp = tid >> 5;
    if (lane == 0) { s_red[wrp] = csum; s_red[4 + wrp] = wsum; }
    __syncthreads();
    if (tid == 0) {
        g_cwt_part[gy * NBX + blockIdx.x] = s_red[0] + s_red[1] + s_red[2] + s_red[3];
        if (gy == 0)
            g_wave_part[blockIdx.x] = s_red[4] + s_red[5] + s_red[6] + s_red[7];
    }

    // Last block finalizes (saves a kernel launch)
    __threadfence();
    if (tid == 0) {
        unsigned old = atomicAdd(&g_done, 1u);
        s_last = (old == TOTALB - 1) ? 1u : 0u;
    }
    __syncthreads();
    if (s_last) {
        double sc = 0.0, sw = 0.0;
        for (int i = tid; i < NGRP * NBX; i += THREADS) sc += (double)__ldcg(&g_cwt_part[i]);
        for (int i = tid; i < NBX; i += THREADS)        sw += (double)__ldcg(&g_wave_part[i]);
        double* rc = reinterpret_cast<double*>(sd);
        double* rw = reinterpret_cast<double*>(sd) + THREADS;
        rc[tid] = sc; rw[tid] = sw;
        __syncthreads();
        #pragma unroll
        for (int s = THREADS / 2; s > 0; s >>= 1) {
            if (tid < s) { rc[tid] += rc[tid + s]; rw[tid] += rw[tid + s]; }
            __syncthreads();
        }
        if (tid == 0) {
            double lw = rw[0] / (double)L_TOTAL;
            double lc = rc[0] / (36.0 * (double)L_TOTAL);
            out[0] = (float)(0.5 * lw + 0.5 * lc);
            g_done = 0;                            // reset for next replay
        }
    }
}

extern "C" void kernel_launch(void* const* d_in, const int* in_sizes, int n_in,
                              void* d_out, int out_size) {
    const float* o = (const float*)d_in[0];
    const float* t = (const float*)d_in[1];
    float* out = (float*)d_out;

    dim3 grid(NBX, NGRP);
    cwt_kernel<<<grid, THREADS>>>(o, t, out);
}

// round 11
// speedup vs baseline: 2.6986x; 2.6986x over previous
#include <cuda_runtime.h>
#include <cuda_bf16.h>
#include <math.h>

// ---------------------------------------------------------------------------
// CombinedLoss via mma.sync (baseline PTX; tcgen05 unavailable at sm_100).
// CWT(o)-CWT(t) = CWT(d). Pad all 36 morlet kernels into one 360-tap window:
//   out[n,i] = sum_p Khat[n,p] * d(i+p-180),  Khat[n,p]=mor_{n+1}[p-180+5(n+1)]
// Per 128-output tile: D[128x40] = A[128x384] * B[40x384]^T (bf16, f32 acc).
// A is Hankel: A[m][k]=win[m+k] -> a-fragments from a packed bf16-pair array
// with (row+8)==(col+8) register sharing (5 LDS per k-step for both m-tiles).
// B-fragments precomputed at compile time directly in mma layout.
// ---------------------------------------------------------------------------

#define L_TOTAL 262144
#define THREADS 128
#define MTILE   128
#define TILES   (L_TOTAL / MTILE)   // 2048
#define TPC     2
#define GRID    (TILES / TPC)       // 1024
#define NW      36
#define NTB     5                   // n-tiles of 8 (widths 1..40; 37..40 pad)
#define KSTEPS  24                  // K = 384
#define WINF    516
#define WI_N    512
#define BF_U32  (KSTEPS * NTB * 32 * 2)   // 7680 u32 = 30 KB

__device__ float g_cwt_part[GRID];
__device__ float g_wave_part[GRID];
__device__ unsigned g_done;

// ======================= constexpr morlet coefficients ======================
__host__ __device__ constexpr double cabs_(double v) { return v < 0.0 ? -v : v; }

__host__ __device__ constexpr double cexp_(double xx) {
    if (xx < -120.0) return 0.0;
    const double LN2_HI = 6.93147180369123816490e-01;
    const double LN2_LO = 1.90821492927058770002e-10;
    const double INV_LN2 = 1.44269504088896338700e+00;
    double nd = xx * INV_LN2;
    int n = (int)(nd >= 0.0 ? nd + 0.5 : nd - 0.5);
    double r = (xx - (double)n * LN2_HI) - (double)n * LN2_LO;
    double term = 1.0, sum = 1.0;
    for (int i = 1; i <= 18; ++i) {
        term *= r / (double)i;
        sum += term;
        if (cabs_(term) < 1e-60) break;
    }
    double p = 1.0, b = (n < 0) ? 0.5 : 2.0;
    int m = (n < 0) ? -n : n;
    while (m) { if (m & 1) p *= b; m >>= 1; if (m) b *= b; }
    return sum * p;
}
__host__ __device__ constexpr double ccos_(double xx) {
    const double PIO2_1  = 1.57079632673412561417e+00;
    const double PIO2_1t = 6.07710050650619224932e-11;
    double ax = xx < 0.0 ? -xx : xx;
    int q = (int)(ax * 0.63661977236758134308 + 0.5);
    double r = (ax - (double)q * PIO2_1) - (double)q * PIO2_1t;
    double r2 = r * r;
    double cs = 1.0, tc = 1.0;
    for (int i = 1; i <= 10; ++i) {
        tc *= -r2 / (double)((2 * i - 1) * (2 * i));
        cs += tc;
        if (cabs_(tc) < 1e-60) break;
    }
    double sn = r, ts = r;
    for (int i = 1; i <= 10; ++i) {
        ts *= -r2 / (double)((2 * i) * (2 * i + 1));
        sn += ts;
        if (cabs_(ts) < 1e-60) break;
    }
    int quad = q & 3;
    return quad == 0 ? cs : quad == 1 ? -sn : quad == 2 ? -cs : sn;
}
__host__ __device__ constexpr double morlet_tap(int w, int p) {
    const double TWO_PI = 6.28318530717958647692;
    const double PI_M025 = 0.75112554446494248286;
    int N = 10 * w;
    double step = (2.0 * TWO_PI) / (double)(N - 1);
    double x = -TWO_PI + (double)p * step;
    double ew = cexp_(-0.5 * (double)(w * w));
    return (ccos_((double)w * x) - ew) * cexp_(-0.5 * x * x) * PI_M025;
}

// ---- constexpr float->bf16 (round-to-nearest-even) ----
__host__ __device__ constexpr unsigned short f2bf(double dv) {
    if (dv == 0.0) return 0;
    unsigned s = dv < 0.0 ? 1u : 0u;
    double x = s ? -dv : dv;
    int e = 127;
    while (x >= 2.0) { x *= 0.5; ++e; }
    while (x < 1.0)  { x *= 2.0; --e; }
    double mf = (x - 1.0) * 128.0;
    int m = (int)mf;
    double rem = mf - (double)m;
    if (rem > 0.5 || (rem == 0.5 && (m & 1))) ++m;
    if (m == 128) { m = 0; ++e; }
    if (e <= 0 || e >= 255) return (unsigned short)(s << 15);
    return (unsigned short)((s << 15) | ((unsigned)e << 7) | (unsigned)m);
}

// Khat[n][p], p in [0,384): mor_{n+1}[p-180+5(n+1)] inside support else 0.
__host__ __device__ constexpr double khat(int n, int p) {
    if (n >= NW) return 0.0;
    int w = n + 1;
    int q = p - 180 + 5 * w;
    if (q < 0 || q >= 10 * w) return 0.0;
    return morlet_tap(w, q);
}

// ---- B fragments in mma.m16n8k16 .col layout ----
// b0 of lane T: (B[k0][n], B[k0+1][n]) with k0=2*(T%4), n=T/4; b1: k0+8.
// Here B[k][n] = Khat[n][16*ks + k].
struct BF { unsigned v[BF_U32]; };
__host__ __device__ constexpr BF make_bf() {
    BF t{};
    for (int ks = 0; ks < KSTEPS; ++ks)
        for (int nt = 0; nt < NTB; ++nt)
            for (int ln = 0; ln < 32; ++ln)
                for (int rg = 0; rg < 2; ++rg) {
                    int n  = nt * 8 + ln / 4;
                    int k0 = 16 * ks + (ln % 4) * 2 + rg * 8;
                    unsigned lo = f2bf(khat(n, k0));
                    unsigned hi = f2bf(khat(n, k0 + 1));
                    t.v[((ks * NTB + nt) * 32 + ln) * 2 + rg] = lo | (hi << 16);
                }
    return t;
}
__device__ __align__(16) const BF g_bf = make_bf();

// ============================ helpers =======================================
__device__ __forceinline__ void mma_bf16(float* d, unsigned a0, unsigned a1,
                                         unsigned a2, unsigned a3,
                                         unsigned b0, unsigned b1) {
    asm volatile(
        "mma.sync.aligned.m16n8k16.row.col.f32.bf16.bf16.f32 "
        "{%0,%1,%2,%3}, {%4,%5,%6,%7}, {%8,%9}, {%0,%1,%2,%3};"
        : "+f"(d[0]), "+f"(d[1]), "+f"(d[2]), "+f"(d[3])
        : "r"(a0), "r"(a1), "r"(a2), "r"(a3), "r"(b0), "r"(b1));
}

__device__ __forceinline__ float warp_sum(float v) {
    #pragma unroll
    for (int o = 16; o > 0; o >>= 1) v += __shfl_xor_sync(0xFFFFFFFFu, v, o);
    return v;
}

// ---------------------------------------------------------------------------
__global__ void __launch_bounds__(THREADS)
cwt_mma_kernel(const float* __restrict__ o, const float* __restrict__ t,
               float* __restrict__ out) {
    __shared__ __align__(16) unsigned sBF[BF_U32];
    __shared__ __align__(8) unsigned sWI[WI_N];
    __shared__ __align__(8) float sWin[WINF];
    __shared__ float s_red[8];
    __shared__ unsigned s_last;
    __shared__ double s_fin[2 * THREADS];

    const int tid  = threadIdx.x;
    const int wid  = tid >> 5;
    const int lane = tid & 31;
    const int mbase = wid * 32;

    // B fragment table -> smem (once per CTA)
    {
        const uint4* src = reinterpret_cast<const uint4*>(g_bf.v);
        uint4* dst = reinterpret_cast<uint4*>(sBF);
        for (int i = tid; i < BF_U32 / 4; i += THREADS) dst[i] = src[i];
    }

    float csum = 0.f, wsum = 0.f;

    for (int it = 0; it < TPC; ++it) {
        const int tile0 = (blockIdx.x * TPC + it) * MTILE;
        __syncthreads();

        // fp32 diff window, zero outside [0,L): sWin[j] = d(tile0 + j - 180)
        for (int j = tid; j < WINF; j += THREADS) {
            int g = tile0 - 180 + j;
            float v = 0.f;
            if (j < 512 && g >= 0 && g < L_TOTAL) v = o[g] - t[g];
            sWin[j] = v;
        }
        __syncthreads();
        // packed bf16 pairs WI[j] = (d_j, d_{j+1}); wave |d| term
        for (int j = tid; j < WI_N; j += THREADS) {
            unsigned lo = (unsigned)__bfloat16_as_ushort(__float2bfloat16(sWin[j]));
            unsigned hi = (unsigned)__bfloat16_as_ushort(__float2bfloat16(sWin[j + 1]));
            sWI[j] = lo | (hi << 16);
        }
        wsum += fabsf(sWin[180 + tid]);
        __syncthreads();

        float acc[2][NTB][4];
        #pragma unroll
        for (int mt = 0; mt < 2; ++mt)
            #pragma unroll
            for (int nt = 0; nt < NTB; ++nt)
                #pragma unroll
                for (int r = 0; r < 4; ++r) acc[mt][nt][r] = 0.f;

        #pragma unroll 1
        for (int ks = 0; ks < KSTEPS; ++ks) {
            // Hankel a-pairs: a0=p0, a1(row+8)=a2(col+8)=p1, a3=p2; mt1: p2..p4
            const int bj = mbase + (lane >> 2) + 16 * ks + 2 * (lane & 3);
            unsigned p0 = sWI[bj];
            unsigned p1 = sWI[bj + 8];
            unsigned p2 = sWI[bj + 16];
            unsigned p3 = sWI[bj + 24];
            unsigned p4 = sWI[bj + 32];
            const unsigned* bf = &sBF[ks * NTB * 64];
            #pragma unroll
            for (int nt = 0; nt < NTB; ++nt) {
                unsigned b0 = bf[nt * 64 + lane * 2];
                unsigned b1 = bf[nt * 64 + lane * 2 + 1];
                mma_bf16(acc[0][nt], p0, p1, p1, p2, b0, b1);
                mma_bf16(acc[1][nt], p2, p3, p3, p4, b0, b1);
            }
        }

        // |D| epilogue. Cols n = nt*8 + 2*(lane%4) + {0,1}; drop n >= 36.
        #pragma unroll
        for (int mt = 0; mt < 2; ++mt) {
            #pragma unroll
            for (int nt = 0; nt < 4; ++nt)
                #pragma unroll
                for (int r = 0; r < 4; ++r) csum += fabsf(acc[mt][nt][r]);
            if ((lane & 3) < 2)
                #pragma unroll
                for (int r = 0; r < 4; ++r) csum += fabsf(acc[mt][4][r]);
        }
    }

    // Block reduction -> per-block partials
    csum = warp_sum(csum);
    wsum = warp_sum(wsum);
    if (lane == 0) { s_red[wid] = csum; s_red[4 + wid] = wsum; }
    __syncthreads();
    if (tid == 0) {
        g_cwt_part[blockIdx.x]  = s_red[0] + s_red[1] + s_red[2] + s_red[3];
        g_wave_part[blockIdx.x] = s_red[4] + s_red[5] + s_red[6] + s_red[7];
    }

    // Last block finalizes
    __threadfence();
    if (tid == 0) {
        unsigned old = atomicAdd(&g_done, 1u);
        s_last = (old == GRID - 1) ? 1u : 0u;
    }
    __syncthreads();
    if (s_last) {
        double sc = 0.0, sw = 0.0;
        for (int i = tid; i < GRID; i += THREADS) {
            sc += (double)__ldcg(&g_cwt_part[i]);
            sw += (double)__ldcg(&g_wave_part[i]);
        }
        s_fin[tid] = sc; s_fin[THREADS + tid] = sw;
        __syncthreads();
        #pragma unroll
        for (int s = THREADS / 2; s > 0; s >>= 1) {
            if (tid < s) {
                s_fin[tid] += s_fin[tid + s];
                s_fin[THREADS + tid] += s_fin[THREADS + tid + s];
            }
            __syncthreads();
        }
        if (tid == 0) {
            double lw = s_fin[THREADS] / (double)L_TOTAL;
            double lc = s_fin[0] / (36.0 * (double)L_TOTAL);
            out[0] = (float)(0.5 * lw + 0.5 * lc);
            g_done = 0;                           // reset for next replay
        }
    }
}

extern "C" void kernel_launch(void* const* d_in, const int* in_sizes, int n_in,
                              void* d_out, int out_size) {
    const float* o = (const float*)d_in[0];
    const float* t = (const float*)d_in[1];
    float* out = (float*)d_out;

    cwt_mma_kernel<<<GRID, THREADS>>>(o, t, out);
}

// round 13
// speedup vs baseline: 3.8335x; 1.4206x over previous
#include <cuda_runtime.h>
#include <cuda_bf16.h>
#include <math.h>

// ---------------------------------------------------------------------------
// CombinedLoss via mma.sync m16n8k16 bf16 (baseline PTX, works on sm_100).
// CWT(o)-CWT(t) = CWT(d). All 36 morlet kernels padded into one 360-tap
// window; per 128-output tile: D[128x40] = A[128x384] * B[40x384]^T.
// A is Hankel -> a-frags from packed bf16-pair array, (row+8)==(col+8) reg
// sharing. B-frags constexpr in mma layout. Round 12/13: per-n-tile K-range
// trimming (78 of 120 (nt,ks) pairs are nonzero -> 35% fewer HMMAs, same math).
// ---------------------------------------------------------------------------

#define L_TOTAL 262144
#define THREADS 128
#define MTILE   128
#define TILES   (L_TOTAL / MTILE)   // 2048
#define TPC     2
#define GRID    (TILES / TPC)       // 1024
#define NW      36
#define NTB     5
#define KSTEPS  24
#define WINF    516
#define WI_N    512
#define NFRAG   78
#define BF_U32  (NFRAG * 64)        // 4992 u32 = 19968 B

__device__ float g_cwt_part[GRID];
__device__ float g_wave_part[GRID];
__device__ unsigned g_done;

// Per-ks first active n-tile, and compact fragment-table prefix offsets.
// nt active for ks iff ks in [KS_LO[nt], KS_HI[nt]]: LO={8,6,3,1,0}, HI={13,16,18,21,23}.
__host__ __device__ constexpr int NMIN[KSTEPS] =
    {4,3,3,2,2,2,1,1,0,0,0,0,0,0,1,1,1,2,2,3,3,3,4,4};
__host__ __device__ constexpr int FOFF[KSTEPS] =
    {0,1,3,5,8,11,14,18,22,27,32,37,42,47,52,56,60,64,67,70,72,74,76,77};

// ======================= constexpr morlet coefficients ======================
__host__ __device__ constexpr double cabs_(double v) { return v < 0.0 ? -v : v; }

__host__ __device__ constexpr double cexp_(double xx) {
    if (xx < -120.0) return 0.0;
    const double LN2_HI = 6.93147180369123816490e-01;
    const double LN2_LO = 1.90821492927058770002e-10;
    const double INV_LN2 = 1.44269504088896338700e+00;
    double nd = xx * INV_LN2;
    int n = (int)(nd >= 0.0 ? nd + 0.5 : nd - 0.5);
    double r = (xx - (double)n * LN2_HI) - (double)n * LN2_LO;
    double term = 1.0, sum = 1.0;
    for (int i = 1; i <= 18; ++i) {
        term *= r / (double)i;
        sum += term;
        if (cabs_(term) < 1e-60) break;
    }
    double p = 1.0, b = (n < 0) ? 0.5 : 2.0;
    int m = (n < 0) ? -n : n;
    while (m) { if (m & 1) p *= b; m >>= 1; if (m) b *= b; }
    return sum * p;
}
__host__ __device__ constexpr double ccos_(double xx) {
    const double PIO2_1  = 1.57079632673412561417e+00;
    const double PIO2_1t = 6.07710050650619224932e-11;
    double ax = xx < 0.0 ? -xx : xx;
    int q = (int)(ax * 0.63661977236758134308 + 0.5);
    double r = (ax - (double)q * PIO2_1) - (double)q * PIO2_1t;
    double r2 = r * r;
    double cs = 1.0, tc = 1.0;
    for (int i = 1; i <= 10; ++i) {
        tc *= -r2 / (double)((2 * i - 1) * (2 * i));
        cs += tc;
        if (cabs_(tc) < 1e-60) break;
    }
    double sn = r, ts = r;
    for (int i = 1; i <= 10; ++i) {
        ts *= -r2 / (double)((2 * i) * (2 * i + 1));
        sn += ts;
        if (cabs_(ts) < 1e-60) break;
    }
    int quad = q & 3;
    return quad == 0 ? cs : quad == 1 ? -sn : quad == 2 ? -cs : sn;
}
__host__ __device__ constexpr double morlet_tap(int w, int p) {
    const double TWO_PI = 6.28318530717958647692;
    const double PI_M025 = 0.75112554446494248286;
    int N = 10 * w;
    double step = (2.0 * TWO_PI) / (double)(N - 1);
    double x = -TWO_PI + (double)p * step;
    double ew = cexp_(-0.5 * (double)(w * w));
    return (ccos_((double)w * x) - ew) * cexp_(-0.5 * x * x) * PI_M025;
}

__host__ __device__ constexpr unsigned short f2bf(double dv) {
    if (dv == 0.0) return 0;
    unsigned s = dv < 0.0 ? 1u : 0u;
    double x = s ? -dv : dv;
    int e = 127;
    while (x >= 2.0) { x *= 0.5; ++e; }
    while (x < 1.0)  { x *= 2.0; --e; }
    double mf = (x - 1.0) * 128.0;
    int m = (int)mf;
    double rem = mf - (double)m;
    if (rem > 0.5 || (rem == 0.5 && (m & 1))) ++m;
    if (m == 128) { m = 0; ++e; }
    if (e <= 0 || e >= 255) return (unsigned short)(s << 15);
    return (unsigned short)((s << 15) | ((unsigned)e << 7) | (unsigned)m);
}

// Khat[n][p] = mor_{n+1}[p-180+5(n+1)] inside support else 0.
__host__ __device__ constexpr double khat(int n, int p) {
    if (n >= NW) return 0.0;
    int w = n + 1;
    int q = p - 180 + 5 * w;
    if (q < 0 || q >= 10 * w) return 0.0;
    return morlet_tap(w, q);
}

// Compact B-fragment table, mma.m16n8k16 .col layout:
// frag (ks,nt), nt >= NMIN[ks], stored at FOFF[ks] + nt - NMIN[ks].
// lane T, reg rg: (B[k0][n], B[k0+1][n]); n = nt*8 + T/4, k0 = 16ks + 2(T%4) + 8rg.
struct BFt { unsigned v[BF_U32]; };
__host__ __device__ constexpr BFt make_bf() {
    BFt t{};
    for (int ks = 0; ks < KSTEPS; ++ks)
        for (int nt = NMIN[ks]; nt < NTB; ++nt) {
            int fi = FOFF[ks] + nt - NMIN[ks];
            for (int ln = 0; ln < 32; ++ln)
                for (int rg = 0; rg < 2; ++rg) {
                    int n  = nt * 8 + ln / 4;
                    int k0 = 16 * ks + (ln % 4) * 2 + rg * 8;
                    unsigned lo = f2bf(khat(n, k0));
                    unsigned hi = f2bf(khat(n, k0 + 1));
                    t.v[(fi * 32 + ln) * 2 + rg] = lo | (hi << 16);
                }
        }
    return t;
}
__device__ __align__(16) const BFt g_bf = make_bf();

// ============================ helpers =======================================
__device__ __forceinline__ void mma_bf16(float* d, unsigned a0, unsigned a1,
                                         unsigned a2, unsigned a3,
                                         unsigned b0, unsigned b1) {
    asm volatile(
        "mma.sync.aligned.m16n8k16.row.col.f32.bf16.bf16.f32 "
        "{%0,%1,%2,%3}, {%4,%5,%6,%7}, {%8,%9}, {%0,%1,%2,%3};"
        : "+f"(d[0]), "+f"(d[1]), "+f"(d[2]), "+f"(d[3])
        : "r"(a0), "r"(a1), "r"(a2), "r"(a3), "r"(b0), "r"(b1));
}

__device__ __forceinline__ float warp_sum(float v) {
    #pragma unroll
    for (int o = 16; o > 0; o >>= 1) v += __shfl_xor_sync(0xFFFFFFFFu, v, o);
    return v;
}

// ---------------------------------------------------------------------------
__global__ void __launch_bounds__(THREADS)
cwt_mma_kernel(const float* __restrict__ o, const float* __restrict__ t,
               float* __restrict__ out) {
    __shared__ __align__(16) unsigned sBF[BF_U32];
    __shared__ __align__(8) unsigned sWI[WI_N];
    __shared__ __align__(8) float sWin[WINF];
    __shared__ float s_red[8];
    __shared__ unsigned s_last;
    __shared__ double s_fin[2 * THREADS];

    const int tid  = threadIdx.x;
    const int wid  = tid >> 5;
    const int lane = tid & 31;
    const int mbase = wid * 32;

    // Compact B fragment table -> smem (once per CTA)
    {
        const uint4* src = reinterpret_cast<const uint4*>(g_bf.v);
        uint4* dst = reinterpret_cast<uint4*>(sBF);
        for (int i = tid; i < BF_U32 / 4; i += THREADS) dst[i] = src[i];
    }

    float csum = 0.f, wsum = 0.f;

    for (int it = 0; it < TPC; ++it) {
        const int tile0 = (blockIdx.x * TPC + it) * MTILE;
        __syncthreads();

        // fp32 diff window, zero outside [0,L): sWin[j] = d(tile0 + j - 180)
        for (int j = tid; j < WINF; j += THREADS) {
            int g = tile0 - 180 + j;
            float v = 0.f;
            if (j < 512 && g >= 0 && g < L_TOTAL) v = o[g] - t[g];
            sWin[j] = v;
        }
        __syncthreads();
        for (int j = tid; j < WI_N; j += THREADS) {
            unsigned lo = (unsigned)__bfloat16_as_ushort(__float2bfloat16(sWin[j]));
            unsigned hi = (unsigned)__bfloat16_as_ushort(__float2bfloat16(sWin[j + 1]));
            sWI[j] = lo | (hi << 16);
        }
        wsum += fabsf(sWin[180 + tid]);
        __syncthreads();

        float acc[2][NTB][4];
        #pragma unroll
        for (int mt = 0; mt < 2; ++mt)
            #pragma unroll
            for (int nt = 0; nt < NTB; ++nt)
                #pragma unroll
                for (int r = 0; r < 4; ++r) acc[mt][nt][r] = 0.f;

        // Fully unrolled: per ks, only active n-tiles (78 pairs of HMMAs total)
        #pragma unroll
        for (int ks = 0; ks < KSTEPS; ++ks) {
            const int bj = mbase + (lane >> 2) + 16 * ks + 2 * (lane & 3);
            unsigned p0 = sWI[bj];
            unsigned p1 = sWI[bj + 8];
            unsigned p2 = sWI[bj + 16];
            unsigned p3 = sWI[bj + 24];
            unsigned p4 = sWI[bj + 32];
            #pragma unroll
            for (int nt = 0; nt < NTB; ++nt) {
                if (nt >= NMIN[ks]) {              // compile-time after unroll
                    const int fi = FOFF[ks] + nt - NMIN[ks];
                    unsigned b0 = sBF[fi * 64 + lane * 2];
                    unsigned b1 = sBF[fi * 64 + lane * 2 + 1];
                    mma_bf16(acc[0][nt], p0, p1, p1, p2, b0, b1);
                    mma_bf16(acc[1][nt], p2, p3, p3, p4, b0, b1);
                }
            }
        }

        // |D| epilogue. Cols n = nt*8 + 2*(lane&3) + {0,1}; drop n >= 36.
        #pragma unroll
        for (int mt = 0; mt < 2; ++mt) {
            #pragma unroll
            for (int nt = 0; nt < 4; ++nt)
                #pragma unroll
                for (int r = 0; r < 4; ++r) csum += fabsf(acc[mt][nt][r]);
            if ((lane & 3) < 2)
                #pragma unroll
                for (int r = 0; r < 4; ++r) csum += fabsf(acc[mt][4][r]);
        }
    }

    // Block reduction -> per-block partials
    csum = warp_sum(csum);
    wsum = warp_sum(wsum);
    if (lane == 0) { s_red[wid] = csum; s_red[4 + wid] = wsum; }
    __syncthreads();
    if (tid == 0) {
        g_cwt_part[blockIdx.x]  = s_red[0] + s_red[1] + s_red[2] + s_red[3];
        g_wave_part[blockIdx.x] = s_red[4] + s_red[5] + s_red[6] + s_red[7];
    }

    // Last block finalizes
    __threadfence();
    if (tid == 0) {
        unsigned old = atomicAdd(&g_done, 1u);
        s_last = (old == GRID - 1) ? 1u : 0u;
    }
    __syncthreads();
    if (s_last) {
        double sc = 0.0, sw = 0.0;
        for (int i = tid; i < GRID; i += THREADS) {
            sc += (double)__ldcg(&g_cwt_part[i]);
            sw += (double)__ldcg(&g_wave_part[i]);
        }
        s_fin[tid] = sc; s_fin[THREADS + tid] = sw;
        __syncthreads();
        #pragma unroll
        for (int s = THREADS / 2; s > 0; s >>= 1) {
            if (tid < s) {
                s_fin[tid] += s_fin[tid + s];
                s_fin[THREADS + tid] += s_fin[THREADS + tid + s];
            }
            __syncthreads();
        }
        if (tid == 0) {
            double lw = s_fin[THREADS] / (double)L_TOTAL;
            double lc = s_fin[0] / (36.0 * (double)L_TOTAL);
            out[0] = (float)(0.5 * lw + 0.5 * lc);
            g_done = 0;                           // reset for next replay
        }
    }
}

extern "C" void kernel_launch(void* const* d_in, const int* in_sizes, int n_in,
                              void* d_out, int out_size) {
    const float* o = (const float*)d_in[0];
    const float* t = (const float*)d_in[1];
    float* out = (float*)d_out;

    cwt_mma_kernel<<<GRID, THREADS>>>(o, t, out);
}